// round 13
// baseline (speedup 1.0000x reference)
#include <cuda_runtime.h>

// ---------------- problem constants ----------------
#define TDIM   2048
#define BDIM   16384
#define NTS    18431            // TDIM + BDIM - 1
#define MQ     24               // seasonality period == HORIZON
#define XOUT_N (BDIM * TDIM)    // 33554432
#define DEN_N  (BDIM * 48)      // 786432

// ---------------- chunk-parallel scan config (R7 layout) ----------------
#define W_UP   1440             // warm-up steps (60 seasonal cycles)
#define WMACRO (W_UP / MQ)      // 60
#define CH_S   19               // output steps per chunk
#define WPB    4                // warps (=chunks) per block
#define K3_BT  (WPB * 32)       // 128 threads
#define K3_NB  243              // 972 chunk slots >= 971 needed
#define NCHUNK 1024             // logical chunk-index space
#define BSPAN  (WPB * CH_S)     // 76 output steps per block
#define SLICE  (W_UP + BSPAN)   // 1516 ts floats used
#define TSBUF  2080             // sm_ts size: >= SLICE+32 pad, >= 2048 for prefix

// ---------------- k_out tiling ----------------
#define ROWS_PB 32                       // rows per xout block
#define XB5     (BDIM / ROWS_PB)         // 512 xout blocks
#define ITERS   (ROWS_PB * 512 / 256)    // 64 float4-iterations per block
#define DB      ((DEN_N + 255) / 256)    // 3072 denorm blocks
#define STAGE   2088                     // staged floats: 31+2047+3 pad, /8

// ---------------- device scratch (no allocs allowed) ----------------
__device__ __align__(16) float g_xn[18448];   // padded: max read 18439
__device__ float g_l [NTS];
__device__ float g_s [NTS];
__device__ float g_lstart[NCHUNK];
__device__ float g_lend  [NCHUNK];
__device__ float g_c     [NCHUNK];
__device__ unsigned g_cnt;                    // zero-init; reset each launch

__device__ __forceinline__ float frcp(float x) {
    float r;
    asm("rcp.approx.ftz.f32 %0, %1;" : "=f"(r) : "f"(x));
    return r;
}

// ============ K1: lane-per-slot warp-parallel ES scan (R7 numerics) ========
// One warp = one 19-step chunk warm-started 1440 steps back. Lane j owns
// seasonal slot j. Level chain solved per 24-step macro by a Kogge-Stone
// affine scan. LAST block to finish runs the 1024-entry prefix product
// (same FP sequence as the old k_prefix kernel -> bitwise-identical g_c).
__global__ __launch_bounds__(K3_BT) void k_scan(
    const float* __restrict__ x,
    const float* __restrict__ alpha_p, const float* __restrict__ gamma_p,
    const float* __restrict__ inits,   const float* __restrict__ level_p)
{
    __shared__ float sm_ts[TSBUF];
    __shared__ float sm_xn[BSPAN];
    __shared__ float sm_l [BSPAN];
    __shared__ float sm_s [BSPAN];
    __shared__ unsigned s_pos;

    const int tid        = threadIdx.x;
    const int wid        = tid >> 5;
    const int lane       = tid & 31;
    const int blk_t0     = blockIdx.x * BSPAN;
    const int slice_base = blk_t0 - W_UP;

    // stage ts slice: ts[u] = (u < T) ? x[0,u,0] : x[u-T+1, T-1, 0]
    for (int idx = tid; idx < SLICE + 32; idx += K3_BT) {
        int u = slice_base + idx;
        float v = 1.0f;
        if (u >= 0 && u < NTS)
            v = (u < TDIM) ? x[u] : x[(u - (TDIM - 1)) * TDIM + (TDIM - 1)];
        sm_ts[idx] = v;
    }
    __syncthreads();

    const float a  = *alpha_p;
    const float g  = *gamma_p;
    const float ka = 1.0f - a;
    const float kg = 1.0f - g;
    const float ka2 = ka * ka, ka4 = ka2 * ka2, ka8 = ka4 * ka4, ka16 = ka8 * ka8;

    const int chunk = blockIdx.x * WPB + wid;
    const int t0    = chunk * CH_S;
    const int u0    = t0 - W_UP;
    const int base  = wid * CH_S;      // sm_ts index of this warp's u0

    // per-lane constant ka^(lane+1)
    float kaPow = ka;
    for (int i = 0; i < lane; i++) kaPow *= ka;

    // lane j owns slot j: q = inits[(j + t0) % 24]
    float q, iq;
    {
        int idx = (lane + t0) % MQ;
        q  = inits[idx];
        iq = frcp(q);
    }
    float l = *level_p;

    int kk = 0;
    // ---- clamped prefix (chunks with t0 < W_UP): skip whole macros; one
    // partial macro where lanes j < rem use identity affines & skip updates.
    if (u0 < 0) {
        int m   = (-u0) / MQ;
        int rem = (-u0) % MQ;
        kk = m;
        if (rem > 0) {
            int off = base + kk * MQ;
            float y = sm_ts[off + lane];
            float r = y * iq;
            bool act = (lane >= rem);
            float Av = act ? ka      : 1.0f;
            float Bv = act ? a * r   : 0.0f;
#pragma unroll
            for (int s = 1; s < MQ; s <<= 1) {
                float Bp = __shfl_up_sync(0xffffffffu, Bv, s);
                float Ap = __shfl_up_sync(0xffffffffu, Av, s);
                if (lane >= s) { Bv = fmaf(Av, Bp, Bv); Av *= Ap; }
            }
            float ll = fmaf(Av, l, Bv);
            if (act) {
                float il = frcp(ll);
                float sn = fmaf(kg, q, (g * y) * il);
                q  = sn;
                iq = frcp(sn);
            }
            l = __shfl_sync(0xffffffffu, ll, MQ - 1);
            kk++;
        }
    }

    // ---- clean warm loop ----
    for (; kk < WMACRO; kk++) {
        float y = sm_ts[base + kk * MQ + lane];
        float r = y * iq;
        float B = a * r;
        float Bp;
        Bp = __shfl_up_sync(0xffffffffu, B, 1);  if (lane >= 1)  B = fmaf(ka,   Bp, B);
        Bp = __shfl_up_sync(0xffffffffu, B, 2);  if (lane >= 2)  B = fmaf(ka2,  Bp, B);
        Bp = __shfl_up_sync(0xffffffffu, B, 4);  if (lane >= 4)  B = fmaf(ka4,  Bp, B);
        Bp = __shfl_up_sync(0xffffffffu, B, 8);  if (lane >= 8)  B = fmaf(ka8,  Bp, B);
        Bp = __shfl_up_sync(0xffffffffu, B, 16); if (lane >= 16) B = fmaf(ka16, Bp, B);
        float ll = fmaf(kaPow, l, B);
        float il = frcp(ll);
        float sn = fmaf(kg, q, (g * y) * il);
        q  = sn;
        iq = frcp(sn);
        l  = __shfl_sync(0xffffffffu, ll, MQ - 1);
    }

    if (lane == 0) g_lstart[chunk] = l;    // level entering t0

    // ---- output phase: 19 steps (lanes 0..18 produce results) ----
    {
        float y = sm_ts[base + WMACRO * MQ + lane];
        float r = y * iq;
        float B = a * r;
        float Bp;
        Bp = __shfl_up_sync(0xffffffffu, B, 1);  if (lane >= 1)  B = fmaf(ka,   Bp, B);
        Bp = __shfl_up_sync(0xffffffffu, B, 2);  if (lane >= 2)  B = fmaf(ka2,  Bp, B);
        Bp = __shfl_up_sync(0xffffffffu, B, 4);  if (lane >= 4)  B = fmaf(ka4,  Bp, B);
        Bp = __shfl_up_sync(0xffffffffu, B, 8);  if (lane >= 8)  B = fmaf(ka8,  Bp, B);
        Bp = __shfl_up_sync(0xffffffffu, B, 16); if (lane >= 16) B = fmaf(ka16, Bp, B);
        float ll = fmaf(kaPow, l, B);
        float il = frcp(ll);
        float sn = fmaf(kg, q, (g * y) * il);
        if (lane < CH_S) {
            int oo = base + lane;
            sm_xn[oo] = r * il;
            sm_l [oo] = ll;
            sm_s [oo] = sn;
        }
        float le = __shfl_sync(0xffffffffu, ll, CH_S - 1);
        if (lane == 0) g_lend[chunk] = le;   // level entering t0 + 19
    }

    __syncthreads();
    int span = NTS - blk_t0; if (span > BSPAN) span = BSPAN;
    for (int idx = tid; idx < span; idx += K3_BT) {
        int t = blk_t0 + idx;
        g_xn[t] = sm_xn[idx];
        g_l [t] = sm_l [idx];
        g_s [t] = sm_s [idx];
    }

    // ---- last-block prefix product (replaces the k_prefix kernel) ----
    __threadfence();
    if (tid == 0) s_pos = atomicAdd(&g_cnt, 1u);
    __syncthreads();
    if (s_pos == K3_NB - 1) {
        float* b0 = sm_ts;          // 1024
        float* b1 = sm_ts + 1024;   // 1024 (TSBUF = 2080 >= 2048)
        for (int k = tid; k < NCHUNK; k += K3_BT) {
            float ratio = 1.0f;
            if (k > 0 && k * CH_S < NTS) ratio = g_lstart[k] / g_lend[k - 1];
            b0[k] = ratio;
        }
        __syncthreads();
        // 10 Hillis-Steele rounds: identical multiply sequence to old k_prefix
        for (int o = 1; o < NCHUNK; o <<= 1) {
            for (int k = tid; k < NCHUNK; k += K3_BT)
                b1[k] = (k >= o) ? b0[k] * b0[k - o] : b0[k];
            __syncthreads();
            float* tmp = b0; b0 = b1; b1 = tmp;
        }
        for (int k = tid; k < NCHUNK; k += K3_BT) g_c[k] = b0[k];
        if (tid == 0) g_cnt = 0;             // deterministic reset for replay
    }
}

// ============ K2: fused x_out + denorm, 4-shifted smem stage ============
// xout block = 32 complete rows (65536 outputs) needing only xn[r0..r0+2081]
// (8.3 KB). Staging builds FOUR shifted copies in smem so that every output
// float4 is exactly ONE conflict-free LDS.128 (shift = row&3, warp-uniform)
// + one streaming STG.128. No mux ALU, no double LDS.
__global__ __launch_bounds__(256) void k_out(float* __restrict__ out) {
    __shared__ __align__(16) float smsh[4][STAGE];
    int bx  = blockIdx.x;
    int tid = threadIdx.x;
    if (bx < XB5) {
        int r0 = bx << 5;                             // first row of the tile
        for (int k = tid; k < STAGE; k += 256) {
            float v = g_xn[r0 + k];                   // max 16352+2087 < 18448
            smsh[0][k] = v;                           // smsh[s][i] = xn[r0+i+s]
            if (k >= 1) smsh[1][k - 1] = v;
            if (k >= 2) smsh[2][k - 2] = v;
            if (k >= 3) smsh[3][k - 3] = v;
        }
        __syncthreads();
        float4* o4 = reinterpret_cast<float4*>(out) + (bx << 14);
#pragma unroll 4
        for (int it = 0; it < ITERS; it++) {
            int j   = it * 256 + tid;                 // float4 index in tile
            int row = j >> 9;                         // 0..31 (warp-uniform)
            int t4  = j & 511;
            int rel = row + (t4 << 2);                // (b-r0) + t
            int sh  = row & 3;                        // warp-uniform
            const float4* p = reinterpret_cast<const float4*>(smsh[sh]);
            __stcs(o4 + j, p[rel >> 2]);
        }
    } else {
        int i = (bx - XB5) * 256 + tid;
        if (i < DEN_N) {
            int b = i / 48;
            int r = i - b * 48;
            int h = r >> 1;
            float v;
            if (r & 1) {
                int t = (TDIM - MQ) + b + h;
                v = g_s[t] * g_c[t / CH_S];          // s_true = s * c
            } else {
                int t = (TDIM - 1) + b;
                v = g_l[t] / g_c[t / CH_S];          // l_true = l / c
            }
            out[XOUT_N + i] = v;
        }
    }
}

extern "C" void kernel_launch(void* const* d_in, const int* in_sizes, int n_in,
                              void* d_out, int out_size) {
    const float* x     = (const float*)d_in[0];
    const float* alpha = (const float*)d_in[1];
    const float* gamma = (const float*)d_in[2];
    const float* inits = (const float*)d_in[3];
    const float* level = (const float*)d_in[4];
    float* out = (float*)d_out;

    k_scan<<<K3_NB, K3_BT>>>(x, alpha, gamma, inits, level);
    int nb = (out_size >= XOUT_N + DEN_N) ? (XB5 + DB) : XB5;
    k_out<<<nb, 256>>>(out);
}

// round 14
// speedup vs baseline: 1.0934x; 1.0934x over previous
#include <cuda_runtime.h>

// ---------------- problem constants ----------------
#define TDIM   2048
#define BDIM   16384
#define NTS    18431            // TDIM + BDIM - 1
#define MQ     24               // seasonality period == HORIZON
#define XOUT_N (BDIM * TDIM)    // 33554432
#define DEN_N  (BDIM * 48)      // 786432

// ---------------- chunk-parallel scan config (R7 layout) ----------------
#define W_UP   1440             // warm-up steps (60 seasonal cycles)
#define WMACRO (W_UP / MQ)      // 60
#define CH_S   19               // output steps per chunk
#define WPB    4                // warps (=chunks) per block
#define K3_BT  (WPB * 32)       // 128 threads
#define K3_NB  243              // 972 chunk slots >= 971 needed
#define NCHUNK 1024             // logical chunk-index space
#define BSPAN  (WPB * CH_S)     // 76 output steps per block
#define SLICE  (W_UP + BSPAN)   // 1516 ts floats used
#define TSBUF  2080             // sm_ts size: >= SLICE+32 pad, >= 2048 for prefix

#define XB     (XOUT_N / 4 / 256)        // 32768 xout blocks
#define DB     ((DEN_N + 255) / 256)     // 3072 denorm blocks

// ---------------- device scratch (no allocs allowed) ----------------
__device__ __align__(16) float g_xn[18448];   // padded: max read idx 18435
__device__ float g_l [NTS];
__device__ float g_s [NTS];
__device__ float g_lstart[NCHUNK];
__device__ float g_lend  [NCHUNK];
__device__ float g_c     [NCHUNK];
__device__ unsigned g_cnt;                    // zero-init; reset each launch

__device__ __forceinline__ float frcp(float x) {
    float r;
    asm("rcp.approx.ftz.f32 %0, %1;" : "=f"(r) : "f"(x));
    return r;
}

// ============ K1: lane-per-slot warp-parallel ES scan (R7 numerics) ========
// One warp = one 19-step chunk warm-started 1440 steps back. Lane j owns
// seasonal slot j. Level chain solved per 24-step macro by a Kogge-Stone
// affine scan. LAST block to finish runs the 1024-entry prefix product
// (same FP sequence as the old k_prefix kernel -> bitwise-identical g_c).
__global__ __launch_bounds__(K3_BT) void k_scan(
    const float* __restrict__ x,
    const float* __restrict__ alpha_p, const float* __restrict__ gamma_p,
    const float* __restrict__ inits,   const float* __restrict__ level_p)
{
    __shared__ float sm_ts[TSBUF];
    __shared__ float sm_xn[BSPAN];
    __shared__ float sm_l [BSPAN];
    __shared__ float sm_s [BSPAN];
    __shared__ unsigned s_pos;

    const int tid        = threadIdx.x;
    const int wid        = tid >> 5;
    const int lane       = tid & 31;
    const int blk_t0     = blockIdx.x * BSPAN;
    const int slice_base = blk_t0 - W_UP;

    // stage ts slice: ts[u] = (u < T) ? x[0,u,0] : x[u-T+1, T-1, 0]
    for (int idx = tid; idx < SLICE + 32; idx += K3_BT) {
        int u = slice_base + idx;
        float v = 1.0f;
        if (u >= 0 && u < NTS)
            v = (u < TDIM) ? x[u] : x[(u - (TDIM - 1)) * TDIM + (TDIM - 1)];
        sm_ts[idx] = v;
    }
    __syncthreads();

    const float a  = *alpha_p;
    const float g  = *gamma_p;
    const float ka = 1.0f - a;
    const float kg = 1.0f - g;
    const float ka2 = ka * ka, ka4 = ka2 * ka2, ka8 = ka4 * ka4, ka16 = ka8 * ka8;

    const int chunk = blockIdx.x * WPB + wid;
    const int t0    = chunk * CH_S;
    const int u0    = t0 - W_UP;
    const int base  = wid * CH_S;      // sm_ts index of this warp's u0

    // per-lane constant ka^(lane+1)
    float kaPow = ka;
    for (int i = 0; i < lane; i++) kaPow *= ka;

    // lane j owns slot j: q = inits[(j + t0) % 24]
    float q, iq;
    {
        int idx = (lane + t0) % MQ;
        q  = inits[idx];
        iq = frcp(q);
    }
    float l = *level_p;

    int kk = 0;
    // ---- clamped prefix (chunks with t0 < W_UP): skip whole macros; one
    // partial macro where lanes j < rem use identity affines & skip updates.
    if (u0 < 0) {
        int m   = (-u0) / MQ;
        int rem = (-u0) % MQ;
        kk = m;
        if (rem > 0) {
            int off = base + kk * MQ;
            float y = sm_ts[off + lane];
            float r = y * iq;
            bool act = (lane >= rem);
            float Av = act ? ka      : 1.0f;
            float Bv = act ? a * r   : 0.0f;
#pragma unroll
            for (int s = 1; s < MQ; s <<= 1) {
                float Bp = __shfl_up_sync(0xffffffffu, Bv, s);
                float Ap = __shfl_up_sync(0xffffffffu, Av, s);
                if (lane >= s) { Bv = fmaf(Av, Bp, Bv); Av *= Ap; }
            }
            float ll = fmaf(Av, l, Bv);
            if (act) {
                float il = frcp(ll);
                float sn = fmaf(kg, q, (g * y) * il);
                q  = sn;
                iq = frcp(sn);
            }
            l = __shfl_sync(0xffffffffu, ll, MQ - 1);
            kk++;
        }
    }

    // ---- clean warm loop ----
    for (; kk < WMACRO; kk++) {
        float y = sm_ts[base + kk * MQ + lane];
        float r = y * iq;
        float B = a * r;
        float Bp;
        Bp = __shfl_up_sync(0xffffffffu, B, 1);  if (lane >= 1)  B = fmaf(ka,   Bp, B);
        Bp = __shfl_up_sync(0xffffffffu, B, 2);  if (lane >= 2)  B = fmaf(ka2,  Bp, B);
        Bp = __shfl_up_sync(0xffffffffu, B, 4);  if (lane >= 4)  B = fmaf(ka4,  Bp, B);
        Bp = __shfl_up_sync(0xffffffffu, B, 8);  if (lane >= 8)  B = fmaf(ka8,  Bp, B);
        Bp = __shfl_up_sync(0xffffffffu, B, 16); if (lane >= 16) B = fmaf(ka16, Bp, B);
        float ll = fmaf(kaPow, l, B);
        float il = frcp(ll);
        float sn = fmaf(kg, q, (g * y) * il);
        q  = sn;
        iq = frcp(sn);
        l  = __shfl_sync(0xffffffffu, ll, MQ - 1);
    }

    if (lane == 0) g_lstart[chunk] = l;    // level entering t0

    // ---- output phase: 19 steps (lanes 0..18 produce results) ----
    {
        float y = sm_ts[base + WMACRO * MQ + lane];
        float r = y * iq;
        float B = a * r;
        float Bp;
        Bp = __shfl_up_sync(0xffffffffu, B, 1);  if (lane >= 1)  B = fmaf(ka,   Bp, B);
        Bp = __shfl_up_sync(0xffffffffu, B, 2);  if (lane >= 2)  B = fmaf(ka2,  Bp, B);
        Bp = __shfl_up_sync(0xffffffffu, B, 4);  if (lane >= 4)  B = fmaf(ka4,  Bp, B);
        Bp = __shfl_up_sync(0xffffffffu, B, 8);  if (lane >= 8)  B = fmaf(ka8,  Bp, B);
        Bp = __shfl_up_sync(0xffffffffu, B, 16); if (lane >= 16) B = fmaf(ka16, Bp, B);
        float ll = fmaf(kaPow, l, B);
        float il = frcp(ll);
        float sn = fmaf(kg, q, (g * y) * il);
        if (lane < CH_S) {
            int oo = base + lane;
            sm_xn[oo] = r * il;
            sm_l [oo] = ll;
            sm_s [oo] = sn;
        }
        float le = __shfl_sync(0xffffffffu, ll, CH_S - 1);
        if (lane == 0) g_lend[chunk] = le;   // level entering t0 + 19
    }

    __syncthreads();
    int span = NTS - blk_t0; if (span > BSPAN) span = BSPAN;
    for (int idx = tid; idx < span; idx += K3_BT) {
        int t = blk_t0 + idx;
        g_xn[t] = sm_xn[idx];
        g_l [t] = sm_l [idx];
        g_s [t] = sm_s [idx];
    }

    // ---- last-block prefix product (replaces the k_prefix kernel) ----
    __threadfence();
    if (tid == 0) s_pos = atomicAdd(&g_cnt, 1u);
    __syncthreads();
    if (s_pos == K3_NB - 1) {
        float* b0 = sm_ts;          // 1024
        float* b1 = sm_ts + 1024;   // 1024 (TSBUF = 2080 >= 2048)
        for (int k = tid; k < NCHUNK; k += K3_BT) {
            float ratio = 1.0f;
            if (k > 0 && k * CH_S < NTS) ratio = g_lstart[k] / g_lend[k - 1];
            b0[k] = ratio;
        }
        __syncthreads();
        // 10 Hillis-Steele rounds: identical multiply sequence to old k_prefix
        for (int o = 1; o < NCHUNK; o <<= 1) {
            for (int k = tid; k < NCHUNK; k += K3_BT)
                b1[k] = (k >= o) ? b0[k] * b0[k - o] : b0[k];
            __syncthreads();
            float* tmp = b0; b0 = b1; b1 = tmp;
        }
        for (int k = tid; k < NCHUNK; k += K3_BT) g_c[k] = b0[k];
        if (tid == 0) g_cnt = 0;             // deterministic reset for replay
    }
}

// ============ K2: fused x_out + denorm, shfl realignment ============
// Source xn is 74 KB -> L1-resident. Each thread: 1 coalesced LDG.128
// (q0 stride 1 across lanes), realign by sh (warp-uniform, sh = b&3) using
// SHFL_DOWN of the neighbor's leading elements (lane 31 patches via scalar
// LDG), then 1 streaming STG.128. No smem, no syncthreads, no staging.
__global__ __launch_bounds__(256) void k_out(float* __restrict__ out) {
    const unsigned FULL = 0xffffffffu;
    int bx  = blockIdx.x;
    int tid = threadIdx.x;
    if (bx < XB) {
        int i4   = bx * 256 + tid;
        int i    = i4 << 2;
        int b    = i >> 11;
        int t    = i & (TDIM - 1);
        int base = b + t;
        int q0   = base >> 2;
        int sh   = base & 3;                 // warp-uniform
        const float4* xn4 = reinterpret_cast<const float4*>(g_xn);
        float4 f = __ldg(&xn4[q0]);
        float4 v;
        bool last = ((tid & 31) == 31);
        int  nb4  = (q0 + 1) << 2;           // g_xn index of next float4
        if (sh == 0) {
            v = f;
        } else if (sh == 1) {
            float nx = __shfl_down_sync(FULL, f.x, 1);
            if (last) nx = __ldg(&g_xn[nb4]);
            v = make_float4(f.y, f.z, f.w, nx);
        } else if (sh == 2) {
            float nx = __shfl_down_sync(FULL, f.x, 1);
            float ny = __shfl_down_sync(FULL, f.y, 1);
            if (last) { nx = __ldg(&g_xn[nb4]); ny = __ldg(&g_xn[nb4 + 1]); }
            v = make_float4(f.z, f.w, nx, ny);
        } else {
            float nx = __shfl_down_sync(FULL, f.x, 1);
            float ny = __shfl_down_sync(FULL, f.y, 1);
            float nz = __shfl_down_sync(FULL, f.z, 1);
            if (last) { nx = __ldg(&g_xn[nb4]); ny = __ldg(&g_xn[nb4 + 1]);
                        nz = __ldg(&g_xn[nb4 + 2]); }
            v = make_float4(f.w, nx, ny, nz);
        }
        __stcs(reinterpret_cast<float4*>(out) + i4, v);
    } else {
        int i = (bx - XB) * 256 + tid;
        if (i < DEN_N) {
            int b = i / 48;
            int r = i - b * 48;
            int h = r >> 1;
            float v;
            if (r & 1) {
                int t = (TDIM - MQ) + b + h;
                v = g_s[t] * g_c[t / CH_S];          // s_true = s * c
            } else {
                int t = (TDIM - 1) + b;
                v = g_l[t] / g_c[t / CH_S];          // l_true = l / c
            }
            out[XOUT_N + i] = v;
        }
    }
}

extern "C" void kernel_launch(void* const* d_in, const int* in_sizes, int n_in,
                              void* d_out, int out_size) {
    const float* x     = (const float*)d_in[0];
    const float* alpha = (const float*)d_in[1];
    const float* gamma = (const float*)d_in[2];
    const float* inits = (const float*)d_in[3];
    const float* level = (const float*)d_in[4];
    float* out = (float*)d_out;

    k_scan<<<K3_NB, K3_BT>>>(x, alpha, gamma, inits, level);
    int nb = (out_size >= XOUT_N + DEN_N) ? (XB + DB) : XB;
    k_out<<<nb, 256>>>(out);
}